// round 5
// baseline (speedup 1.0000x reference)
#include <cuda_runtime.h>
#include <math.h>

// Problem constants
#define BB   2
#define SS   2048
#define DMODEL 2048
#define NH   16
#define DH   128
#define MTOT (BB*SS)          // 4096 rows for the projection GEMMs

// ---------------------------------------------------------------------------
// Scratch (allocation-free rule: __device__ globals)
// ---------------------------------------------------------------------------
__device__ float g_Q[(size_t)BB*NH*SS*DH];   // [B,H,S,Dh] 32MB
__device__ float g_K[(size_t)BB*NH*SS*DH];   // 32MB
__device__ float g_V[(size_t)BB*NH*SS*DH];   // 32MB
__device__ float g_O[(size_t)BB*SS*DMODEL];  // [B,S,D]   32MB

// ---------------------------------------------------------------------------
// GEMM:  C[m][n] = sum_k A[m][k] * W[n][k]
//   A: [M=4096, K=2048] row-major,  W: [N=2048, K=2048] row-major
// mode 0: C row-major [M, N]           (final output projection)
// mode 1: C scattered to [B,H,S,Dh]    (Q/K/V projections, head split)
// Tiles: 128x128x16, 8x8 per thread, 256 threads.
// ---------------------------------------------------------------------------
__global__ __launch_bounds__(256, 2)
void gemm_nt_kernel(const float* __restrict__ A, const float* __restrict__ W,
                    float* __restrict__ C, int mode)
{
    __shared__ float As[16][132];   // [k][m], padded
    __shared__ float Bs[16][132];   // [k][n], padded

    const int tid = threadIdx.x;
    const int tr  = tid >> 4;       // 0..15
    const int tc  = tid & 15;       // 0..15
    const int bm  = blockIdx.y;
    const int bn  = blockIdx.x;

    const float* Ag = A + (size_t)bm * 128 * DMODEL;
    const float* Wg = W + (size_t)bn * 128 * DMODEL;

    float acc[8][8];
#pragma unroll
    for (int i = 0; i < 8; i++)
#pragma unroll
        for (int j = 0; j < 8; j++) acc[i][j] = 0.f;

    for (int k0 = 0; k0 < DMODEL; k0 += 16) {
        // stage A and W tiles (transposed into [k][row]) — 2 float4 each / thread
#pragma unroll
        for (int t = 0; t < 2; t++) {
            int idx = tid + t * 256;          // 0..511
            int m   = idx >> 2;               // 0..127
            int k4  = (idx & 3) << 2;         // 0,4,8,12
            float4 va = *(const float4*)(Ag + (size_t)m * DMODEL + k0 + k4);
            As[k4+0][m] = va.x; As[k4+1][m] = va.y;
            As[k4+2][m] = va.z; As[k4+3][m] = va.w;
            float4 vb = *(const float4*)(Wg + (size_t)m * DMODEL + k0 + k4);
            Bs[k4+0][m] = vb.x; Bs[k4+1][m] = vb.y;
            Bs[k4+2][m] = vb.z; Bs[k4+3][m] = vb.w;
        }
        __syncthreads();

#pragma unroll
        for (int k = 0; k < 16; k++) {
            float a[8], b[8];
            *(float4*)&a[0] = *(float4*)&As[k][tr*8];
            *(float4*)&a[4] = *(float4*)&As[k][tr*8+4];
            *(float4*)&b[0] = *(float4*)&Bs[k][tc*8];
            *(float4*)&b[4] = *(float4*)&Bs[k][tc*8+4];
#pragma unroll
            for (int i = 0; i < 8; i++)
#pragma unroll
                for (int j = 0; j < 8; j++)
                    acc[i][j] = fmaf(a[i], b[j], acc[i][j]);
        }
        __syncthreads();
    }

    if (mode == 0) {
#pragma unroll
        for (int i = 0; i < 8; i++) {
            int m = bm*128 + tr*8 + i;
            float* dst = C + (size_t)m * DMODEL + bn*128 + tc*8;
            *(float4*)dst       = make_float4(acc[i][0], acc[i][1], acc[i][2], acc[i][3]);
            *(float4*)(dst + 4) = make_float4(acc[i][4], acc[i][5], acc[i][6], acc[i][7]);
        }
    } else {
        // head-split scatter: col -> (h, d); block's 128 cols are exactly one head
        int col0 = bn*128 + tc*8;
        int h = col0 >> 7;
        int d = col0 & 127;
#pragma unroll
        for (int i = 0; i < 8; i++) {
            int m = bm*128 + tr*8 + i;
            int b = m >> 11;           // / 2048
            int s = m & 2047;
            float* dst = C + ((size_t)((b*NH + h)*SS + s)) * DH + d;
            *(float4*)dst       = make_float4(acc[i][0], acc[i][1], acc[i][2], acc[i][3]);
            *(float4*)(dst + 4) = make_float4(acc[i][4], acc[i][5], acc[i][6], acc[i][7]);
        }
    }
}

// ---------------------------------------------------------------------------
// "RoPE" exactly as the reference computes it. NOTE: the reference's
// _rotate_half slices with HEAD_DIM (=128, the FULL head dim), so x2 is an
// empty slice and rotate_half(x) == x. Hence:
//     q_out[d] = q[d] * (cos(f_d) + sin(f_d)),  f_d = s * inv_freq[d mod 64]
// i.e. a pure elementwise scaling of Q and K. One thread per element.
// ---------------------------------------------------------------------------
__global__ void rope_kernel(float* __restrict__ Q, float* __restrict__ K)
{
    int idx = blockIdx.x * blockDim.x + threadIdx.x;   // BB*NH*SS*DH total
    int d  = idx & 127;
    int s  = (idx >> 7) & (SS - 1);
    int bh = idx >> 18;                                 // / (128*2048)
    size_t off = (((size_t)bh * SS + s) << 7) + d;

    int j = d & 63;   // emb = concat([freqs, freqs]) -> freq index = d mod 64
    // inv_freq = 10000^(-2j/128); ln(10000) = 9.210340371976184
    float inv = expf(-(float)(2*j) * (9.210340371976184f / 128.0f));
    float f = (float)s * inv;
    float sn, cs;
    sincosf(f, &sn, &cs);
    float fac = cs + sn;

    Q[off] *= fac;
    K[off] *= fac;
}

// ---------------------------------------------------------------------------
// Causal flash attention, fp32.
// Grid: (S/64, H, B). Block: 256 threads (16x16), 4x4 score tile / thread,
// 4x8 output tile / thread. Online softmax with half-warp shfl reductions.
// Writes O in [B,S,D] layout (ready for the output projection GEMM).
// ---------------------------------------------------------------------------
#define BQ 64
#define BKT 64
#define ATTN_SMEM ((128*64 + 128*64 + 64*128 + 64*64) * sizeof(float))  // 114688B

__global__ __launch_bounds__(256, 1)
void attn_kernel(const float* __restrict__ Q, const float* __restrict__ K,
                 const float* __restrict__ V, float* __restrict__ O)
{
    extern __shared__ float sm[];
    float* Qs = sm;                 // [128][64]  d-major
    float* Ks = Qs + 128*64;        // [128][64]  d-major
    float* Vs = Ks + 128*64;        // [64][128]  row-major
    float* Ps = Vs + 64*128;        // [64][64]

    const int tid = threadIdx.x;
    const int tr  = tid >> 4;       // 0..15 -> q rows tr*4..tr*4+3
    const int tc  = tid & 15;       // 0..15 -> score cols tc*4.., O cols tc*8..
    const int qt  = blockIdx.x;
    const int h   = blockIdx.y;
    const int b   = blockIdx.z;

    const size_t base = ((size_t)(b*NH + h)) * SS * DH;
    const float* Qg = Q + base + (size_t)qt * BQ * DH;
    const float* Kg = K + base;
    const float* Vg = V + base;

    // load Q tile transposed into Qs[d][r]
#pragma unroll
    for (int t = 0; t < 8; t++) {
        int lin = tid + t * 256;     // 0..2047 (float4 units)
        int r   = lin >> 5;          // 0..63
        int d4  = (lin & 31) << 2;   // 0..124
        float4 v = *(const float4*)(Qg + (size_t)r * DH + d4);
        Qs[(d4+0)*64 + r] = v.x;
        Qs[(d4+1)*64 + r] = v.y;
        Qs[(d4+2)*64 + r] = v.z;
        Qs[(d4+3)*64 + r] = v.w;
    }

    float o[4][8];
#pragma unroll
    for (int i = 0; i < 4; i++)
#pragma unroll
        for (int c = 0; c < 8; c++) o[i][c] = 0.f;
    float mrow[4], lrow[4];
#pragma unroll
    for (int i = 0; i < 4; i++) { mrow[i] = -INFINITY; lrow[i] = 0.f; }

    const float scale = 0.08838834764831845f;   // 1/sqrt(128)

    for (int kt = 0; kt <= qt; kt++) {
        __syncthreads();   // previous PV reads done before overwriting tiles
        // load K tile (transposed) and V tile (direct)
#pragma unroll
        for (int t = 0; t < 8; t++) {
            int lin = tid + t * 256;
            int r   = lin >> 5;
            int d4  = (lin & 31) << 2;
            float4 v = *(const float4*)(Kg + (size_t)(kt*BKT + r) * DH + d4);
            Ks[(d4+0)*64 + r] = v.x;
            Ks[(d4+1)*64 + r] = v.y;
            Ks[(d4+2)*64 + r] = v.z;
            Ks[(d4+3)*64 + r] = v.w;
            float4 w = *(const float4*)(Vg + (size_t)(kt*BKT + r) * DH + d4);
            *(float4*)&Vs[r*DH + d4] = w;
        }
        __syncthreads();

        // scores: s4[i][j] = Q[tr*4+i] . K[tc*4+j]
        float s4[4][4];
#pragma unroll
        for (int i = 0; i < 4; i++)
#pragma unroll
            for (int j = 0; j < 4; j++) s4[i][j] = 0.f;

#pragma unroll 8
        for (int d = 0; d < DH; d++) {
            float4 qa = *(float4*)&Qs[d*64 + tr*4];
            float4 kb = *(float4*)&Ks[d*64 + tc*4];
            s4[0][0] = fmaf(qa.x, kb.x, s4[0][0]);
            s4[0][1] = fmaf(qa.x, kb.y, s4[0][1]);
            s4[0][2] = fmaf(qa.x, kb.z, s4[0][2]);
            s4[0][3] = fmaf(qa.x, kb.w, s4[0][3]);
            s4[1][0] = fmaf(qa.y, kb.x, s4[1][0]);
            s4[1][1] = fmaf(qa.y, kb.y, s4[1][1]);
            s4[1][2] = fmaf(qa.y, kb.z, s4[1][2]);
            s4[1][3] = fmaf(qa.y, kb.w, s4[1][3]);
            s4[2][0] = fmaf(qa.z, kb.x, s4[2][0]);
            s4[2][1] = fmaf(qa.z, kb.y, s4[2][1]);
            s4[2][2] = fmaf(qa.z, kb.z, s4[2][2]);
            s4[2][3] = fmaf(qa.z, kb.w, s4[2][3]);
            s4[3][0] = fmaf(qa.w, kb.x, s4[3][0]);
            s4[3][1] = fmaf(qa.w, kb.y, s4[3][1]);
            s4[3][2] = fmaf(qa.w, kb.z, s4[3][2]);
            s4[3][3] = fmaf(qa.w, kb.w, s4[3][3]);
        }

        const bool diag = (kt == qt);
#pragma unroll
        for (int i = 0; i < 4; i++) {
            int ig = qt*BQ + tr*4 + i;
#pragma unroll
            for (int j = 0; j < 4; j++) {
                s4[i][j] *= scale;
                if (diag) {
                    int jg = kt*BKT + tc*4 + j;
                    if (jg > ig) s4[i][j] = -INFINITY;
                }
            }
            // row max across the 16-thread (half-warp) row group
            float mx = fmaxf(fmaxf(s4[i][0], s4[i][1]), fmaxf(s4[i][2], s4[i][3]));
            mx = fmaxf(mx, __shfl_xor_sync(0xffffffffu, mx, 8));
            mx = fmaxf(mx, __shfl_xor_sync(0xffffffffu, mx, 4));
            mx = fmaxf(mx, __shfl_xor_sync(0xffffffffu, mx, 2));
            mx = fmaxf(mx, __shfl_xor_sync(0xffffffffu, mx, 1));
            float newm = fmaxf(mrow[i], mx);
            float sum = 0.f;
#pragma unroll
            for (int j = 0; j < 4; j++) {
                float p = __expf(s4[i][j] - newm);
                s4[i][j] = p;
                sum += p;
            }
            sum += __shfl_xor_sync(0xffffffffu, sum, 8);
            sum += __shfl_xor_sync(0xffffffffu, sum, 4);
            sum += __shfl_xor_sync(0xffffffffu, sum, 2);
            sum += __shfl_xor_sync(0xffffffffu, sum, 1);
            float alpha = __expf(mrow[i] - newm);
            lrow[i] = lrow[i]*alpha + sum;
            mrow[i] = newm;
#pragma unroll
            for (int c = 0; c < 8; c++) o[i][c] *= alpha;
            *(float4*)&Ps[(tr*4+i)*64 + tc*4] =
                make_float4(s4[i][0], s4[i][1], s4[i][2], s4[i][3]);
        }
        __syncthreads();

        // O[4x8] += P[4x64] @ V[64x8]
#pragma unroll 4
        for (int kk = 0; kk < BKT; kk++) {
            float4 va = *(float4*)&Vs[kk*DH + tc*8];
            float4 vb = *(float4*)&Vs[kk*DH + tc*8 + 4];
            float pr[4];
#pragma unroll
            for (int i = 0; i < 4; i++) pr[i] = Ps[(tr*4+i)*64 + kk];
#pragma unroll
            for (int i = 0; i < 4; i++) {
                o[i][0] = fmaf(pr[i], va.x, o[i][0]);
                o[i][1] = fmaf(pr[i], va.y, o[i][1]);
                o[i][2] = fmaf(pr[i], va.z, o[i][2]);
                o[i][3] = fmaf(pr[i], va.w, o[i][3]);
                o[i][4] = fmaf(pr[i], vb.x, o[i][4]);
                o[i][5] = fmaf(pr[i], vb.y, o[i][5]);
                o[i][6] = fmaf(pr[i], vb.z, o[i][6]);
                o[i][7] = fmaf(pr[i], vb.w, o[i][7]);
            }
        }
    }

    // normalize and write to [B,S,D] layout
    float* Og = O + ((size_t)b * SS) * DMODEL + (size_t)h * DH;
#pragma unroll
    for (int i = 0; i < 4; i++) {
        int q = qt*BQ + tr*4 + i;
        float inv = 1.0f / lrow[i];
        *(float4*)(Og + (size_t)q * DMODEL + tc*8) =
            make_float4(o[i][0]*inv, o[i][1]*inv, o[i][2]*inv, o[i][3]*inv);
        *(float4*)(Og + (size_t)q * DMODEL + tc*8 + 4) =
            make_float4(o[i][4]*inv, o[i][5]*inv, o[i][6]*inv, o[i][7]*inv);
    }
}

// ---------------------------------------------------------------------------
// Launch. d_in[0] is x (verified: 8,388,608 elements slot); metadata order is
// the setup_inputs() insertion order: x, attention_mask, Wq, Wk, Wv, Wd.
// ---------------------------------------------------------------------------
extern "C" void kernel_launch(void* const* d_in, const int* in_sizes, int n_in,
                              void* d_out, int out_size)
{
    (void)out_size;
    const int X_ELEMS = MTOT * DMODEL;   // 8,388,608

    const float *x, *Wq, *Wk, *Wv, *Wd;
    if (n_in >= 6 && in_sizes[0] == X_ELEMS) {
        // insertion order: x, mask, Wq, Wk, Wv, Wd
        x  = (const float*)d_in[0];
        Wq = (const float*)d_in[2];
        Wk = (const float*)d_in[3];
        Wv = (const float*)d_in[4];
        Wd = (const float*)d_in[5];
    } else {
        // fallback: sorted order Wd, Wk, Wq, Wv, attention_mask, x
        Wd = (const float*)d_in[0];
        Wk = (const float*)d_in[1];
        Wq = (const float*)d_in[2];
        Wv = (const float*)d_in[3];
        x  = (const float*)d_in[5];
    }
    float* out = (float*)d_out;

    float *Qp, *Kp, *Vp, *Op;
    cudaGetSymbolAddress((void**)&Qp, g_Q);
    cudaGetSymbolAddress((void**)&Kp, g_K);
    cudaGetSymbolAddress((void**)&Vp, g_V);
    cudaGetSymbolAddress((void**)&Op, g_O);

    dim3 ggrid(DMODEL/128, MTOT/128);   // (16, 32)

    gemm_nt_kernel<<<ggrid, 256>>>(x, Wq, Qp, 1);
    gemm_nt_kernel<<<ggrid, 256>>>(x, Wk, Kp, 1);
    gemm_nt_kernel<<<ggrid, 256>>>(x, Wv, Vp, 1);

    rope_kernel<<<(BB*NH*SS*DH)/256, 256>>>(Qp, Kp);

    cudaFuncSetAttribute(attn_kernel,
                         cudaFuncAttributeMaxDynamicSharedMemorySize,
                         (int)ATTN_SMEM);
    attn_kernel<<<dim3(SS/BQ, NH, BB), 256, ATTN_SMEM>>>(Qp, Kp, Vp, Op);

    gemm_nt_kernel<<<ggrid, 256>>>(Op, Wd, out, 0);
}

// round 6
// speedup vs baseline: 1.6154x; 1.6154x over previous
#include <cuda_runtime.h>
#include <cuda_bf16.h>
#include <math.h>

// Problem constants
#define BB   2
#define SS   2048
#define DMODEL 2048
#define NH   16
#define DH   128
#define MTOT (BB*SS)          // 4096 rows for the projection GEMMs

// ---------------------------------------------------------------------------
// Scratch (allocation-free rule: __device__ globals)
// ---------------------------------------------------------------------------
__device__ float g_Q[(size_t)BB*NH*SS*DH];   // [B,H,S,Dh] 32MB
__device__ float g_K[(size_t)BB*NH*SS*DH];   // 32MB
__device__ float g_V[(size_t)BB*NH*SS*DH];   // 32MB
__device__ float g_O[(size_t)BB*SS*DMODEL];  // [B,S,D]   32MB

// ---------------------------------------------------------------------------
// Tensor-core GEMM (bf16 split-3):  C[m][n] = sum_k A[m][k] * W[n][k]
//   A: [4096, 2048] fp32 row-major,  W: [2048, 2048] fp32 row-major.
// Accuracy: a = a_hi + a_lo (bf16 each); C ~= Ah*Wh + Ah*Wl + Al*Wh
// (dropped al*wl term ~2^-18 relative).
// Block tile 128x128, 512 threads (16 warps), warp tile 32x32, k-chunk 32,
// double-buffered smem (2 x 32KB), XOR-swizzled bf16 tiles, ldmatrix + HMMA.
// mode 0: C row-major [M, N]; mode 1: C scattered to [B,H,S,Dh].
// ---------------------------------------------------------------------------
#define GSTAGE 32768              // bytes per stage: 4 tiles x 8KB
#define GSMEM  (2*GSTAGE)         // 64KB

__device__ __forceinline__ void ldsm4(unsigned* r, unsigned addr) {
    asm volatile("ldmatrix.sync.aligned.m8n8.x4.shared.b16 {%0,%1,%2,%3}, [%4];\n"
        : "=r"(r[0]), "=r"(r[1]), "=r"(r[2]), "=r"(r[3]) : "r"(addr));
}

__device__ __forceinline__ void mma16816(float* c, const unsigned* a,
                                         unsigned b0, unsigned b1) {
    asm volatile(
        "mma.sync.aligned.m16n8k16.row.col.f32.bf16.bf16.f32 "
        "{%0,%1,%2,%3}, {%4,%5,%6,%7}, {%8,%9}, {%0,%1,%2,%3};\n"
        : "+f"(c[0]), "+f"(c[1]), "+f"(c[2]), "+f"(c[3])
        : "r"(a[0]), "r"(a[1]), "r"(a[2]), "r"(a[3]), "r"(b0), "r"(b1));
}

__global__ __launch_bounds__(512, 1)
void gemm_bf16x3_kernel(const float* __restrict__ A, const float* __restrict__ W,
                        float* __restrict__ C, int mode)
{
    extern __shared__ __align__(16) char smem[];
    // stage layout: A_hi @0, A_lo @8192, W_hi @16384, W_lo @24576 (each 128x32 bf16)

    const int t    = threadIdx.x;
    const int lane = t & 31;
    const int wid  = t >> 5;
    const int warpM = wid >> 2;          // 0..3
    const int warpN = wid & 3;           // 0..3
    const int m_base = warpM * 32;
    const int n_base = warpN * 32;
    const int bm = blockIdx.y;
    const int bn = blockIdx.x;
    const int g  = lane >> 2;            // 0..7
    const int tg = lane & 3;             // 0..3

    const unsigned smem_u32 = (unsigned)__cvta_generic_to_shared(smem);

    const float* Ag = A + (size_t)(bm * 128) * DMODEL;
    const float* Wg = W + (size_t)(bn * 128) * DMODEL;

    float acc[2][4][4];
#pragma unroll
    for (int mi = 0; mi < 2; mi++)
#pragma unroll
        for (int j = 0; j < 4; j++)
#pragma unroll
            for (int e = 0; e < 4; e++) acc[mi][j][e] = 0.f;

    // staging registers (2 float4 of A + 2 of W per stage per thread)
    float4 ra[2], rw[2];
    // chunk idx = t + i*512 -> row = idx>>3, kq = idx&7 (float4 within 32-k row)
    int rowi[2], kqi[2];
#pragma unroll
    for (int i = 0; i < 2; i++) {
        int idx = t + i * 512;
        rowi[i] = idx >> 3;
        kqi[i]  = idx & 7;
    }

#define LOAD_STAGE(K0)                                                          \
    do {                                                                        \
        _Pragma("unroll")                                                       \
        for (int i = 0; i < 2; i++) {                                           \
            ra[i] = *(const float4*)(Ag + (size_t)rowi[i] * DMODEL + (K0) + kqi[i] * 4); \
            rw[i] = *(const float4*)(Wg + (size_t)rowi[i] * DMODEL + (K0) + kqi[i] * 4); \
        }                                                                       \
    } while (0)

#define STORE_STAGE(BUF)                                                        \
    do {                                                                        \
        char* sb = smem + (BUF) * GSTAGE;                                       \
        _Pragma("unroll")                                                       \
        for (int i = 0; i < 2; i++) {                                           \
            int row = rowi[i], kq = kqi[i];                                     \
            unsigned off = (unsigned)(row * 64 + (((kq >> 1) ^ ((row >> 1) & 3)) << 4) + ((kq & 1) << 3)); \
            /* A hi/lo */                                                       \
            __nv_bfloat162 h0 = __floats2bfloat162_rn(ra[i].x, ra[i].y);        \
            __nv_bfloat162 h1 = __floats2bfloat162_rn(ra[i].z, ra[i].w);        \
            float l0 = ra[i].x - __bfloat162float(h0.x);                        \
            float l1 = ra[i].y - __bfloat162float(h0.y);                        \
            float l2 = ra[i].z - __bfloat162float(h1.x);                        \
            float l3 = ra[i].w - __bfloat162float(h1.y);                        \
            __nv_bfloat162 s0 = __floats2bfloat162_rn(l0, l1);                  \
            __nv_bfloat162 s1 = __floats2bfloat162_rn(l2, l3);                  \
            *(uint2*)(sb + off)        = make_uint2(*(unsigned*)&h0, *(unsigned*)&h1); \
            *(uint2*)(sb + 8192 + off) = make_uint2(*(unsigned*)&s0, *(unsigned*)&s1); \
            /* W hi/lo */                                                       \
            h0 = __floats2bfloat162_rn(rw[i].x, rw[i].y);                       \
            h1 = __floats2bfloat162_rn(rw[i].z, rw[i].w);                       \
            l0 = rw[i].x - __bfloat162float(h0.x);                              \
            l1 = rw[i].y - __bfloat162float(h0.y);                              \
            l2 = rw[i].z - __bfloat162float(h1.x);                              \
            l3 = rw[i].w - __bfloat162float(h1.y);                              \
            s0 = __floats2bfloat162_rn(l0, l1);                                 \
            s1 = __floats2bfloat162_rn(l2, l3);                                 \
            *(uint2*)(sb + 16384 + off) = make_uint2(*(unsigned*)&h0, *(unsigned*)&h1); \
            *(uint2*)(sb + 24576 + off) = make_uint2(*(unsigned*)&s0, *(unsigned*)&s1); \
        }                                                                       \
    } while (0)

    // prologue: stage 0
    LOAD_STAGE(0);
    STORE_STAGE(0);
    __syncthreads();

    const int NSTAGES = DMODEL / 32;   // 64
    for (int ks = 0; ks < NSTAGES; ks++) {
        if (ks + 1 < NSTAGES) LOAD_STAGE((ks + 1) * 32);

        // compute on buffer ks&1
        const unsigned base = smem_u32 + (unsigned)((ks & 1) * GSTAGE);
#pragma unroll
        for (int s = 0; s < 2; s++) {
            unsigned ah[2][4], al[2][4], bh[2][4], bl[2][4];
            const int kb = s * 2 + (lane >> 4);
#pragma unroll
            for (int mi = 0; mi < 2; mi++) {
                int row = m_base + mi * 16 + (lane & 15);
                unsigned off = (unsigned)(row * 64 + ((kb ^ ((row >> 1) & 3)) << 4));
                ldsm4(ah[mi], base + off);
                ldsm4(al[mi], base + 8192u + off);
            }
#pragma unroll
            for (int ng = 0; ng < 2; ng++) {
                int row = n_base + ng * 16 + (lane & 15);
                unsigned off = (unsigned)(row * 64 + ((kb ^ ((row >> 1) & 3)) << 4));
                ldsm4(bh[ng], base + 16384u + off);
                ldsm4(bl[ng], base + 24576u + off);
            }
#pragma unroll
            for (int mi = 0; mi < 2; mi++) {
#pragma unroll
                for (int j = 0; j < 4; j++) {
                    unsigned bh0 = bh[j >> 1][j & 1], bh1 = bh[j >> 1][(j & 1) + 2];
                    unsigned bl0 = bl[j >> 1][j & 1], bl1 = bl[j >> 1][(j & 1) + 2];
                    mma16816(acc[mi][j], ah[mi], bh0, bh1);
                    mma16816(acc[mi][j], ah[mi], bl0, bl1);
                    mma16816(acc[mi][j], al[mi], bh0, bh1);
                }
            }
        }

        if (ks + 1 < NSTAGES) STORE_STAGE((ks + 1) & 1);
        __syncthreads();
    }

    // epilogue
#pragma unroll
    for (int mi = 0; mi < 2; mi++) {
#pragma unroll
        for (int j = 0; j < 4; j++) {
            int m0  = bm * 128 + m_base + mi * 16 + g;
            int col = n_base + j * 8 + tg * 2;        // 0..127 within block
            float2 v0 = make_float2(acc[mi][j][0], acc[mi][j][1]);
            float2 v1 = make_float2(acc[mi][j][2], acc[mi][j][3]);
            if (mode == 0) {
                *(float2*)(C + (size_t)m0 * DMODEL + bn * 128 + col)       = v0;
                *(float2*)(C + (size_t)(m0 + 8) * DMODEL + bn * 128 + col) = v1;
            } else {
                // head-split scatter: head = bn, d = col
                int b0 = m0 >> 11, s0 = m0 & 2047;
                int m1 = m0 + 8;
                int b1 = m1 >> 11, s1 = m1 & 2047;
                *(float2*)(C + ((size_t)(b0 * NH + bn) * SS + s0) * DH + col) = v0;
                *(float2*)(C + ((size_t)(b1 * NH + bn) * SS + s1) * DH + col) = v1;
            }
        }
    }
#undef LOAD_STAGE
#undef STORE_STAGE
}

// ---------------------------------------------------------------------------
// "RoPE" exactly as the reference computes it (rotate_half == identity):
//     q_out[d] = q[d] * (cos(f_d) + sin(f_d)),  f_d = s * inv_freq[d mod 64]
// ---------------------------------------------------------------------------
__global__ void rope_kernel(float* __restrict__ Q, float* __restrict__ K)
{
    int idx = blockIdx.x * blockDim.x + threadIdx.x;   // BB*NH*SS*DH total
    int d  = idx & 127;
    int s  = (idx >> 7) & (SS - 1);
    int bh = idx >> 18;
    size_t off = (((size_t)bh * SS + s) << 7) + d;

    int j = d & 63;
    float inv = expf(-(float)(2*j) * (9.210340371976184f / 128.0f));
    float f = (float)s * inv;
    float sn, cs;
    sincosf(f, &sn, &cs);
    float fac = cs + sn;

    Q[off] *= fac;
    K[off] *= fac;
}

// ---------------------------------------------------------------------------
// Causal flash attention, fp32 (unchanged from round 5).
// ---------------------------------------------------------------------------
#define BQ 64
#define BKT 64
#define ATTN_SMEM ((128*64 + 128*64 + 64*128 + 64*64) * sizeof(float))  // 114688B

__global__ __launch_bounds__(256, 1)
void attn_kernel(const float* __restrict__ Q, const float* __restrict__ K,
                 const float* __restrict__ V, float* __restrict__ O)
{
    extern __shared__ float sm[];
    float* Qs = sm;                 // [128][64]  d-major
    float* Ks = Qs + 128*64;        // [128][64]  d-major
    float* Vs = Ks + 128*64;        // [64][128]  row-major
    float* Ps = Vs + 64*128;        // [64][64]

    const int tid = threadIdx.x;
    const int tr  = tid >> 4;
    const int tc  = tid & 15;
    const int qt  = blockIdx.x;
    const int h   = blockIdx.y;
    const int b   = blockIdx.z;

    const size_t base = ((size_t)(b*NH + h)) * SS * DH;
    const float* Qg = Q + base + (size_t)qt * BQ * DH;
    const float* Kg = K + base;
    const float* Vg = V + base;

#pragma unroll
    for (int t = 0; t < 8; t++) {
        int lin = tid + t * 256;
        int r   = lin >> 5;
        int d4  = (lin & 31) << 2;
        float4 v = *(const float4*)(Qg + (size_t)r * DH + d4);
        Qs[(d4+0)*64 + r] = v.x;
        Qs[(d4+1)*64 + r] = v.y;
        Qs[(d4+2)*64 + r] = v.z;
        Qs[(d4+3)*64 + r] = v.w;
    }

    float o[4][8];
#pragma unroll
    for (int i = 0; i < 4; i++)
#pragma unroll
        for (int c = 0; c < 8; c++) o[i][c] = 0.f;
    float mrow[4], lrow[4];
#pragma unroll
    for (int i = 0; i < 4; i++) { mrow[i] = -INFINITY; lrow[i] = 0.f; }

    const float scale = 0.08838834764831845f;

    for (int kt = 0; kt <= qt; kt++) {
        __syncthreads();
#pragma unroll
        for (int t = 0; t < 8; t++) {
            int lin = tid + t * 256;
            int r   = lin >> 5;
            int d4  = (lin & 31) << 2;
            float4 v = *(const float4*)(Kg + (size_t)(kt*BKT + r) * DH + d4);
            Ks[(d4+0)*64 + r] = v.x;
            Ks[(d4+1)*64 + r] = v.y;
            Ks[(d4+2)*64 + r] = v.z;
            Ks[(d4+3)*64 + r] = v.w;
            float4 w = *(const float4*)(Vg + (size_t)(kt*BKT + r) * DH + d4);
            *(float4*)&Vs[r*DH + d4] = w;
        }
        __syncthreads();

        float s4[4][4];
#pragma unroll
        for (int i = 0; i < 4; i++)
#pragma unroll
            for (int j = 0; j < 4; j++) s4[i][j] = 0.f;

#pragma unroll 8
        for (int d = 0; d < DH; d++) {
            float4 qa = *(float4*)&Qs[d*64 + tr*4];
            float4 kb = *(float4*)&Ks[d*64 + tc*4];
            s4[0][0] = fmaf(qa.x, kb.x, s4[0][0]);
            s4[0][1] = fmaf(qa.x, kb.y, s4[0][1]);
            s4[0][2] = fmaf(qa.x, kb.z, s4[0][2]);
            s4[0][3] = fmaf(qa.x, kb.w, s4[0][3]);
            s4[1][0] = fmaf(qa.y, kb.x, s4[1][0]);
            s4[1][1] = fmaf(qa.y, kb.y, s4[1][1]);
            s4[1][2] = fmaf(qa.y, kb.z, s4[1][2]);
            s4[1][3] = fmaf(qa.y, kb.w, s4[1][3]);
            s4[2][0] = fmaf(qa.z, kb.x, s4[2][0]);
            s4[2][1] = fmaf(qa.z, kb.y, s4[2][1]);
            s4[2][2] = fmaf(qa.z, kb.z, s4[2][2]);
            s4[2][3] = fmaf(qa.z, kb.w, s4[2][3]);
            s4[3][0] = fmaf(qa.w, kb.x, s4[3][0]);
            s4[3][1] = fmaf(qa.w, kb.y, s4[3][1]);
            s4[3][2] = fmaf(qa.w, kb.z, s4[3][2]);
            s4[3][3] = fmaf(qa.w, kb.w, s4[3][3]);
        }

        const bool diag = (kt == qt);
#pragma unroll
        for (int i = 0; i < 4; i++) {
            int ig = qt*BQ + tr*4 + i;
#pragma unroll
            for (int j = 0; j < 4; j++) {
                s4[i][j] *= scale;
                if (diag) {
                    int jg = kt*BKT + tc*4 + j;
                    if (jg > ig) s4[i][j] = -INFINITY;
                }
            }
            float mx = fmaxf(fmaxf(s4[i][0], s4[i][1]), fmaxf(s4[i][2], s4[i][3]));
            mx = fmaxf(mx, __shfl_xor_sync(0xffffffffu, mx, 8));
            mx = fmaxf(mx, __shfl_xor_sync(0xffffffffu, mx, 4));
            mx = fmaxf(mx, __shfl_xor_sync(0xffffffffu, mx, 2));
            mx = fmaxf(mx, __shfl_xor_sync(0xffffffffu, mx, 1));
            float newm = fmaxf(mrow[i], mx);
            float sum = 0.f;
#pragma unroll
            for (int j = 0; j < 4; j++) {
                float p = __expf(s4[i][j] - newm);
                s4[i][j] = p;
                sum += p;
            }
            sum += __shfl_xor_sync(0xffffffffu, sum, 8);
            sum += __shfl_xor_sync(0xffffffffu, sum, 4);
            sum += __shfl_xor_sync(0xffffffffu, sum, 2);
            sum += __shfl_xor_sync(0xffffffffu, sum, 1);
            float alpha = __expf(mrow[i] - newm);
            lrow[i] = lrow[i]*alpha + sum;
            mrow[i] = newm;
#pragma unroll
            for (int c = 0; c < 8; c++) o[i][c] *= alpha;
            *(float4*)&Ps[(tr*4+i)*64 + tc*4] =
                make_float4(s4[i][0], s4[i][1], s4[i][2], s4[i][3]);
        }
        __syncthreads();

#pragma unroll 4
        for (int kk = 0; kk < BKT; kk++) {
            float4 va = *(float4*)&Vs[kk*DH + tc*8];
            float4 vb = *(float4*)&Vs[kk*DH + tc*8 + 4];
            float pr[4];
#pragma unroll
            for (int i = 0; i < 4; i++) pr[i] = Ps[(tr*4+i)*64 + kk];
#pragma unroll
            for (int i = 0; i < 4; i++) {
                o[i][0] = fmaf(pr[i], va.x, o[i][0]);
                o[i][1] = fmaf(pr[i], va.y, o[i][1]);
                o[i][2] = fmaf(pr[i], va.z, o[i][2]);
                o[i][3] = fmaf(pr[i], va.w, o[i][3]);
                o[i][4] = fmaf(pr[i], vb.x, o[i][4]);
                o[i][5] = fmaf(pr[i], vb.y, o[i][5]);
                o[i][6] = fmaf(pr[i], vb.z, o[i][6]);
                o[i][7] = fmaf(pr[i], vb.w, o[i][7]);
            }
        }
    }

    float* Og = O + ((size_t)b * SS) * DMODEL + (size_t)h * DH;
#pragma unroll
    for (int i = 0; i < 4; i++) {
        int q = qt*BQ + tr*4 + i;
        float inv = 1.0f / lrow[i];
        *(float4*)(Og + (size_t)q * DMODEL + tc*8) =
            make_float4(o[i][0]*inv, o[i][1]*inv, o[i][2]*inv, o[i][3]*inv);
        *(float4*)(Og + (size_t)q * DMODEL + tc*8 + 4) =
            make_float4(o[i][4]*inv, o[i][5]*inv, o[i][6]*inv, o[i][7]*inv);
    }
}

// ---------------------------------------------------------------------------
// Launch
// ---------------------------------------------------------------------------
extern "C" void kernel_launch(void* const* d_in, const int* in_sizes, int n_in,
                              void* d_out, int out_size)
{
    (void)out_size;
    const int X_ELEMS = MTOT * DMODEL;   // 8,388,608

    const float *x, *Wq, *Wk, *Wv, *Wd;
    if (n_in >= 6 && in_sizes[0] == X_ELEMS) {
        x  = (const float*)d_in[0];
        Wq = (const float*)d_in[2];
        Wk = (const float*)d_in[3];
        Wv = (const float*)d_in[4];
        Wd = (const float*)d_in[5];
    } else {
        Wd = (const float*)d_in[0];
        Wk = (const float*)d_in[1];
        Wq = (const float*)d_in[2];
        Wv = (const float*)d_in[3];
        x  = (const float*)d_in[5];
    }
    float* out = (float*)d_out;

    float *Qp, *Kp, *Vp, *Op;
    cudaGetSymbolAddress((void**)&Qp, g_Q);
    cudaGetSymbolAddress((void**)&Kp, g_K);
    cudaGetSymbolAddress((void**)&Vp, g_V);
    cudaGetSymbolAddress((void**)&Op, g_O);

    dim3 ggrid(DMODEL/128, MTOT/128);   // (16, 32)

    cudaFuncSetAttribute(gemm_bf16x3_kernel,
                         cudaFuncAttributeMaxDynamicSharedMemorySize, GSMEM);

    gemm_bf16x3_kernel<<<ggrid, 512, GSMEM>>>(x, Wq, Qp, 1);
    gemm_bf16x3_kernel<<<ggrid, 512, GSMEM>>>(x, Wk, Kp, 1);
    gemm_bf16x3_kernel<<<ggrid, 512, GSMEM>>>(x, Wv, Vp, 1);

    rope_kernel<<<(BB*NH*SS*DH)/256, 256>>>(Qp, Kp);

    cudaFuncSetAttribute(attn_kernel,
                         cudaFuncAttributeMaxDynamicSharedMemorySize,
                         (int)ATTN_SMEM);
    attn_kernel<<<dim3(SS/BQ, NH, BB), 256, ATTN_SMEM>>>(Qp, Kp, Vp, Op);

    gemm_bf16x3_kernel<<<ggrid, 512, GSMEM>>>(Op, Wd, out, 0);
}

// round 7
// speedup vs baseline: 2.7447x; 1.6991x over previous
#include <cuda_runtime.h>
#include <cuda_bf16.h>
#include <math.h>

// Problem constants
#define BB   2
#define SS   2048
#define DMODEL 2048
#define NH   16
#define DH   128
#define MTOT (BB*SS)

// ---------------------------------------------------------------------------
// Scratch
// ---------------------------------------------------------------------------
__device__ float g_Q[(size_t)BB*NH*SS*DH];   // [B,H,S,Dh]
__device__ float g_K[(size_t)BB*NH*SS*DH];
__device__ float g_V[(size_t)BB*NH*SS*DH];
__device__ float g_O[(size_t)BB*SS*DMODEL];  // [B,S,D]

// ---------------------------------------------------------------------------
// MMA helpers
// ---------------------------------------------------------------------------
__device__ __forceinline__ void ldsm4(unsigned* r, unsigned addr) {
    asm volatile("ldmatrix.sync.aligned.m8n8.x4.shared.b16 {%0,%1,%2,%3}, [%4];\n"
        : "=r"(r[0]), "=r"(r[1]), "=r"(r[2]), "=r"(r[3]) : "r"(addr));
}

__device__ __forceinline__ void mma16816(float* c, const unsigned* a,
                                         unsigned b0, unsigned b1) {
    asm volatile(
        "mma.sync.aligned.m16n8k16.row.col.f32.bf16.bf16.f32 "
        "{%0,%1,%2,%3}, {%4,%5,%6,%7}, {%8,%9}, {%0,%1,%2,%3};\n"
        : "+f"(c[0]), "+f"(c[1]), "+f"(c[2]), "+f"(c[3])
        : "r"(a[0]), "r"(a[1]), "r"(a[2]), "r"(a[3]), "r"(b0), "r"(b1));
}

__device__ __forceinline__ unsigned packbf2(float x, float y) {
    __nv_bfloat162 t = __floats2bfloat162_rn(x, y);
    return *(unsigned*)&t;
}

// RoPE factor as the reference computes it (rotate_half == identity):
// fac(s,d) = cos(s*inv_freq[d&63]) + sin(s*inv_freq[d&63])
__device__ __forceinline__ float rope_fac(int s, int d) {
    int j = d & 63;
    float inv = expf(-(float)(2*j) * (9.210340371976184f / 128.0f));
    float f = (float)s * inv;
    float sn, cs;
    sincosf(f, &sn, &cs);
    return cs + sn;
}

// ---------------------------------------------------------------------------
// Tensor-core GEMM (bf16 split-3):  C[m][n] = sum_k A[m][k] * W[n][k]
// mode 0: C row-major [M,N]; mode 1: scatter [B,H,S,Dh]; mode 2: scatter+RoPE
// ---------------------------------------------------------------------------
#define GSTAGE 32768
#define GSMEM  (2*GSTAGE)

__global__ __launch_bounds__(512, 1)
void gemm_bf16x3_kernel(const float* __restrict__ A, const float* __restrict__ W,
                        float* __restrict__ C, int mode)
{
    extern __shared__ __align__(16) char smem[];

    const int t    = threadIdx.x;
    const int lane = t & 31;
    const int wid  = t >> 5;
    const int warpM = wid >> 2;
    const int warpN = wid & 3;
    const int m_base = warpM * 32;
    const int n_base = warpN * 32;
    const int bm = blockIdx.y;
    const int bn = blockIdx.x;
    const int g  = lane >> 2;
    const int tg = lane & 3;

    const unsigned smem_u32 = (unsigned)__cvta_generic_to_shared(smem);

    const float* Ag = A + (size_t)(bm * 128) * DMODEL;
    const float* Wg = W + (size_t)(bn * 128) * DMODEL;

    float acc[2][4][4];
#pragma unroll
    for (int mi = 0; mi < 2; mi++)
#pragma unroll
        for (int j = 0; j < 4; j++)
#pragma unroll
            for (int e = 0; e < 4; e++) acc[mi][j][e] = 0.f;

    float4 ra[2], rw[2];
    int rowi[2], kqi[2];
#pragma unroll
    for (int i = 0; i < 2; i++) {
        int idx = t + i * 512;
        rowi[i] = idx >> 3;
        kqi[i]  = idx & 7;
    }

#define LOAD_STAGE(K0)                                                          \
    do {                                                                        \
        _Pragma("unroll")                                                       \
        for (int i = 0; i < 2; i++) {                                           \
            ra[i] = *(const float4*)(Ag + (size_t)rowi[i] * DMODEL + (K0) + kqi[i] * 4); \
            rw[i] = *(const float4*)(Wg + (size_t)rowi[i] * DMODEL + (K0) + kqi[i] * 4); \
        }                                                                       \
    } while (0)

#define STORE_STAGE(BUF)                                                        \
    do {                                                                        \
        char* sb = smem + (BUF) * GSTAGE;                                       \
        _Pragma("unroll")                                                       \
        for (int i = 0; i < 2; i++) {                                           \
            int row = rowi[i], kq = kqi[i];                                     \
            unsigned off = (unsigned)(row * 64 + (((kq >> 1) ^ ((row >> 1) & 3)) << 4) + ((kq & 1) << 3)); \
            __nv_bfloat162 h0 = __floats2bfloat162_rn(ra[i].x, ra[i].y);        \
            __nv_bfloat162 h1 = __floats2bfloat162_rn(ra[i].z, ra[i].w);        \
            float l0 = ra[i].x - __bfloat162float(h0.x);                        \
            float l1 = ra[i].y - __bfloat162float(h0.y);                        \
            float l2 = ra[i].z - __bfloat162float(h1.x);                        \
            float l3 = ra[i].w - __bfloat162float(h1.y);                        \
            __nv_bfloat162 s0 = __floats2bfloat162_rn(l0, l1);                  \
            __nv_bfloat162 s1 = __floats2bfloat162_rn(l2, l3);                  \
            *(uint2*)(sb + off)        = make_uint2(*(unsigned*)&h0, *(unsigned*)&h1); \
            *(uint2*)(sb + 8192 + off) = make_uint2(*(unsigned*)&s0, *(unsigned*)&s1); \
            h0 = __floats2bfloat162_rn(rw[i].x, rw[i].y);                       \
            h1 = __floats2bfloat162_rn(rw[i].z, rw[i].w);                       \
            l0 = rw[i].x - __bfloat162float(h0.x);                              \
            l1 = rw[i].y - __bfloat162float(h0.y);                              \
            l2 = rw[i].z - __bfloat162float(h1.x);                              \
            l3 = rw[i].w - __bfloat162float(h1.y);                              \
            s0 = __floats2bfloat162_rn(l0, l1);                                 \
            s1 = __floats2bfloat162_rn(l2, l3);                                 \
            *(uint2*)(sb + 16384 + off) = make_uint2(*(unsigned*)&h0, *(unsigned*)&h1); \
            *(uint2*)(sb + 24576 + off) = make_uint2(*(unsigned*)&s0, *(unsigned*)&s1); \
        }                                                                       \
    } while (0)

    LOAD_STAGE(0);
    STORE_STAGE(0);
    __syncthreads();

    const int NSTAGES = DMODEL / 32;
    for (int ks = 0; ks < NSTAGES; ks++) {
        if (ks + 1 < NSTAGES) LOAD_STAGE((ks + 1) * 32);

        const unsigned base = smem_u32 + (unsigned)((ks & 1) * GSTAGE);
#pragma unroll
        for (int s = 0; s < 2; s++) {
            unsigned ah[2][4], al[2][4], bh[2][4], bl[2][4];
            const int kb = s * 2 + (lane >> 4);
#pragma unroll
            for (int mi = 0; mi < 2; mi++) {
                int row = m_base + mi * 16 + (lane & 15);
                unsigned off = (unsigned)(row * 64 + ((kb ^ ((row >> 1) & 3)) << 4));
                ldsm4(ah[mi], base + off);
                ldsm4(al[mi], base + 8192u + off);
            }
#pragma unroll
            for (int ng = 0; ng < 2; ng++) {
                int row = n_base + ng * 16 + (lane & 15);
                unsigned off = (unsigned)(row * 64 + ((kb ^ ((row >> 1) & 3)) << 4));
                ldsm4(bh[ng], base + 16384u + off);
                ldsm4(bl[ng], base + 24576u + off);
            }
#pragma unroll
            for (int mi = 0; mi < 2; mi++) {
#pragma unroll
                for (int j = 0; j < 4; j++) {
                    unsigned bh0 = bh[j >> 1][j & 1], bh1 = bh[j >> 1][(j & 1) + 2];
                    unsigned bl0 = bl[j >> 1][j & 1], bl1 = bl[j >> 1][(j & 1) + 2];
                    mma16816(acc[mi][j], ah[mi], bh0, bh1);
                    mma16816(acc[mi][j], ah[mi], bl0, bl1);
                    mma16816(acc[mi][j], al[mi], bh0, bh1);
                }
            }
        }

        if (ks + 1 < NSTAGES) STORE_STAGE((ks + 1) & 1);
        __syncthreads();
    }

#pragma unroll
    for (int mi = 0; mi < 2; mi++) {
#pragma unroll
        for (int j = 0; j < 4; j++) {
            int m0  = bm * 128 + m_base + mi * 16 + g;
            int col = n_base + j * 8 + tg * 2;
            float2 v0 = make_float2(acc[mi][j][0], acc[mi][j][1]);
            float2 v1 = make_float2(acc[mi][j][2], acc[mi][j][3]);
            if (mode == 0) {
                *(float2*)(C + (size_t)m0 * DMODEL + bn * 128 + col)       = v0;
                *(float2*)(C + (size_t)(m0 + 8) * DMODEL + bn * 128 + col) = v1;
            } else {
                int b0 = m0 >> 11, s0 = m0 & 2047;
                int m1 = m0 + 8;
                int b1 = m1 >> 11, s1 = m1 & 2047;
                if (mode == 2) {
                    v0.x *= rope_fac(s0, col);
                    v0.y *= rope_fac(s0, col + 1);
                    v1.x *= rope_fac(s1, col);
                    v1.y *= rope_fac(s1, col + 1);
                }
                *(float2*)(C + ((size_t)(b0 * NH + bn) * SS + s0) * DH + col) = v0;
                *(float2*)(C + ((size_t)(b1 * NH + bn) * SS + s1) * DH + col) = v1;
            }
        }
    }
#undef LOAD_STAGE
#undef STORE_STAGE
}

// ---------------------------------------------------------------------------
// Tensor-core causal flash attention, bf16 split-3 for both QK^T and PV.
// Block: 256 threads (8 warps), BQ=128 (16 rows/warp), BK=64.
// smem: Qh/Ql [128][128]bf16, Kh/Kl [64][128]bf16, Vth/Vtl [128(d)][64(kk)]bf16
// ---------------------------------------------------------------------------
#define AQH 0
#define AQL 32768
#define AKH 65536
#define AKL 81920
#define AVH 98304
#define AVL 114688
#define ATT_SMEM 131072

__global__ __launch_bounds__(256, 1)
void attn_mma_kernel(const float* __restrict__ Q, const float* __restrict__ K,
                     const float* __restrict__ V, float* __restrict__ O)
{
    extern __shared__ __align__(16) char smem[];
    const unsigned sb = (unsigned)__cvta_generic_to_shared(smem);

    const int tid  = threadIdx.x;
    const int lane = tid & 31;
    const int w    = tid >> 5;        // warp 0..7, owns q rows w*16..w*16+15
    const int g    = lane >> 2;       // 0..7
    const int qd   = lane & 3;        // 0..3
    const int qt   = blockIdx.x;
    const int h    = blockIdx.y;
    const int b    = blockIdx.z;

    const size_t base = ((size_t)(b*NH + h)) * SS * DH;
    const float* Qg = Q + base + (size_t)qt * 128 * DH;
    const float* Kg = K + base;
    const float* Vg = V + base;

    // ---- load Q tile (128x128) -> Qh/Ql bf16, swizzled 256B rows ----
#pragma unroll
    for (int tt = 0; tt < 16; tt++) {
        int lin = tid + tt * 256;       // 0..4095 float4 units
        int r   = lin >> 5;             // 0..127
        int d4  = lin & 31;             // 0..31
        float4 v = *(const float4*)(Qg + (size_t)r * DH + d4 * 4);
        int u = d4 >> 1, half = d4 & 1;
        unsigned off = (unsigned)(r * 256 + ((u ^ (r & 7)) << 4) + (half << 3));
        __nv_bfloat162 h0 = __floats2bfloat162_rn(v.x, v.y);
        __nv_bfloat162 h1 = __floats2bfloat162_rn(v.z, v.w);
        __nv_bfloat162 l0 = __floats2bfloat162_rn(v.x - __bfloat162float(h0.x),
                                                  v.y - __bfloat162float(h0.y));
        __nv_bfloat162 l1 = __floats2bfloat162_rn(v.z - __bfloat162float(h1.x),
                                                  v.w - __bfloat162float(h1.y));
        *(uint2*)(smem + AQH + off) = make_uint2(*(unsigned*)&h0, *(unsigned*)&h1);
        *(uint2*)(smem + AQL + off) = make_uint2(*(unsigned*)&l0, *(unsigned*)&l1);
    }

    float o[16][4];
#pragma unroll
    for (int nj = 0; nj < 16; nj++)
#pragma unroll
        for (int e = 0; e < 4; e++) o[nj][e] = 0.f;
    float mrow[2] = {-INFINITY, -INFINITY};
    float lrow[2] = {0.f, 0.f};

    const float scale = 0.08838834764831845f;   // 1/sqrt(128)
    const int ktmax = 2 * qt + 1;

    for (int kt = 0; kt <= ktmax; kt++) {
        __syncthreads();
        // ---- load K tile (64x128) -> Kh/Kl ----
#pragma unroll
        for (int tt = 0; tt < 8; tt++) {
            int lin = tid + tt * 256;   // 0..2047
            int r   = lin >> 5;         // 0..63
            int d4  = lin & 31;
            float4 v = *(const float4*)(Kg + (size_t)(kt*64 + r) * DH + d4 * 4);
            int u = d4 >> 1, half = d4 & 1;
            unsigned off = (unsigned)(r * 256 + ((u ^ (r & 7)) << 4) + (half << 3));
            __nv_bfloat162 h0 = __floats2bfloat162_rn(v.x, v.y);
            __nv_bfloat162 h1 = __floats2bfloat162_rn(v.z, v.w);
            __nv_bfloat162 l0 = __floats2bfloat162_rn(v.x - __bfloat162float(h0.x),
                                                      v.y - __bfloat162float(h0.y));
            __nv_bfloat162 l1 = __floats2bfloat162_rn(v.z - __bfloat162float(h1.x),
                                                      v.w - __bfloat162float(h1.y));
            *(uint2*)(smem + AKH + off) = make_uint2(*(unsigned*)&h0, *(unsigned*)&h1);
            *(uint2*)(smem + AKL + off) = make_uint2(*(unsigned*)&l0, *(unsigned*)&l1);
        }
        // ---- load V tile (64x128) transposed -> Vth/Vtl [d][kk], 128B rows ----
#pragma unroll
        for (int tt = 0; tt < 8; tt++) {
            int lin = tid + tt * 256;
            int kk  = lin & 63;         // key index
            int d4  = lin >> 6;         // 0..31
            float4 v = *(const float4*)(Vg + (size_t)(kt*64 + kk) * DH + d4 * 4);
            float vs[4] = {v.x, v.y, v.z, v.w};
#pragma unroll
            for (int dd = 0; dd < 4; dd++) {
                int d = d4 * 4 + dd;
                unsigned off = (unsigned)(d * 128 + (((kk >> 3) ^ (d & 7)) << 4) + ((kk & 7) << 1));
                __nv_bfloat16 hi = __float2bfloat16(vs[dd]);
                __nv_bfloat16 lo = __float2bfloat16(vs[dd] - __bfloat162float(hi));
                *(__nv_bfloat16*)(smem + AVH + off) = hi;
                *(__nv_bfloat16*)(smem + AVL + off) = lo;
            }
        }
        __syncthreads();

        // ---- S = Q K^T (split-3) ----
        float s[8][4];
#pragma unroll
        for (int nj = 0; nj < 8; nj++)
#pragma unroll
            for (int e = 0; e < 4; e++) s[nj][e] = 0.f;

#pragma unroll
        for (int ks = 0; ks < 8; ks++) {
            unsigned ah[4], al[4];
            {
                int row = w * 16 + (lane & 15);
                int u = 2 * ks + (lane >> 4);
                unsigned off = (unsigned)(row * 256 + ((u ^ (row & 7)) << 4));
                ldsm4(ah, sb + AQH + off);
                ldsm4(al, sb + AQL + off);
            }
#pragma unroll
            for (int g4 = 0; g4 < 4; g4++) {
                unsigned bh[4], bl[4];
                int row = g4 * 16 + (lane & 15);
                int u = 2 * ks + (lane >> 4);
                unsigned off = (unsigned)(row * 256 + ((u ^ (row & 7)) << 4));
                ldsm4(bh, sb + AKH + off);
                ldsm4(bl, sb + AKL + off);
#pragma unroll
                for (int jj = 0; jj < 2; jj++) {
                    int nj = 2 * g4 + jj;
                    mma16816(s[nj], ah, bh[jj], bh[jj + 2]);
                    mma16816(s[nj], ah, bl[jj], bl[jj + 2]);
                    mma16816(s[nj], al, bh[jj], bh[jj + 2]);
                }
            }
        }

        // ---- scale + causal mask ----
        const int r0 = qt * 128 + w * 16 + g;
        const int r1 = r0 + 8;
        const bool tail = (kt >= 2 * qt);
#pragma unroll
        for (int nj = 0; nj < 8; nj++) {
            int c0 = kt * 64 + nj * 8 + qd * 2;
#pragma unroll
            for (int e = 0; e < 4; e++) {
                s[nj][e] *= scale;
                if (tail) {
                    int col = c0 + (e & 1);
                    int row = (e < 2) ? r0 : r1;
                    if (col > row) s[nj][e] = -INFINITY;
                }
            }
        }

        // ---- online softmax (per row-half) ----
        float alpha[2];
#pragma unroll
        for (int half = 0; half < 2; half++) {
            float mx = -INFINITY;
#pragma unroll
            for (int nj = 0; nj < 8; nj++)
                mx = fmaxf(mx, fmaxf(s[nj][2*half], s[nj][2*half+1]));
            mx = fmaxf(mx, __shfl_xor_sync(0xffffffffu, mx, 1));
            mx = fmaxf(mx, __shfl_xor_sync(0xffffffffu, mx, 2));
            float newm = fmaxf(mrow[half], mx);
            float sum = 0.f;
#pragma unroll
            for (int nj = 0; nj < 8; nj++) {
                float p0 = __expf(s[nj][2*half]   - newm);
                float p1 = __expf(s[nj][2*half+1] - newm);
                s[nj][2*half]   = p0;
                s[nj][2*half+1] = p1;
                sum += p0 + p1;
            }
            sum += __shfl_xor_sync(0xffffffffu, sum, 1);
            sum += __shfl_xor_sync(0xffffffffu, sum, 2);
            alpha[half] = __expf(mrow[half] - newm);
            lrow[half] = lrow[half] * alpha[half] + sum;
            mrow[half] = newm;
        }
#pragma unroll
        for (int nj = 0; nj < 16; nj++) {
            o[nj][0] *= alpha[0]; o[nj][1] *= alpha[0];
            o[nj][2] *= alpha[1]; o[nj][3] *= alpha[1];
        }

        // ---- O += P V (split-3); S C-frag reused as P A-frag ----
#pragma unroll
        for (int tpv = 0; tpv < 4; tpv++) {
            unsigned pah[4], pal[4];
            {
                float p00 = s[2*tpv][0],   p01 = s[2*tpv][1];
                float p02 = s[2*tpv][2],   p03 = s[2*tpv][3];
                float p10 = s[2*tpv+1][0], p11 = s[2*tpv+1][1];
                float p12 = s[2*tpv+1][2], p13 = s[2*tpv+1][3];
                __nv_bfloat162 h;
                h = __floats2bfloat162_rn(p00, p01); pah[0] = *(unsigned*)&h;
                pal[0] = packbf2(p00 - __bfloat162float(h.x), p01 - __bfloat162float(h.y));
                h = __floats2bfloat162_rn(p02, p03); pah[1] = *(unsigned*)&h;
                pal[1] = packbf2(p02 - __bfloat162float(h.x), p03 - __bfloat162float(h.y));
                h = __floats2bfloat162_rn(p10, p11); pah[2] = *(unsigned*)&h;
                pal[2] = packbf2(p10 - __bfloat162float(h.x), p11 - __bfloat162float(h.y));
                h = __floats2bfloat162_rn(p12, p13); pah[3] = *(unsigned*)&h;
                pal[3] = packbf2(p12 - __bfloat162float(h.x), p13 - __bfloat162float(h.y));
            }
#pragma unroll
            for (int g4 = 0; g4 < 8; g4++) {
                unsigned vbh[4], vbl[4];
                int row = g4 * 16 + (lane & 15);
                int u = 2 * tpv + (lane >> 4);
                unsigned off = (unsigned)(row * 128 + ((u ^ (row & 7)) << 4));
                ldsm4(vbh, sb + AVH + off);
                ldsm4(vbl, sb + AVL + off);
#pragma unroll
                for (int jj = 0; jj < 2; jj++) {
                    int njo = 2 * g4 + jj;
                    mma16816(o[njo], pah, vbh[jj], vbh[jj + 2]);
                    mma16816(o[njo], pah, vbl[jj], vbl[jj + 2]);
                    mma16816(o[njo], pal, vbh[jj], vbh[jj + 2]);
                }
            }
        }
    }

    // ---- normalize + write [B,S,D] ----
    const float inv0 = 1.f / lrow[0];
    const float inv1 = 1.f / lrow[1];
    const int r0 = qt * 128 + w * 16 + g;
    const int r1 = r0 + 8;
    float* Og = O + (size_t)b * SS * DMODEL + (size_t)h * DH;
#pragma unroll
    for (int njo = 0; njo < 16; njo++) {
        int col = njo * 8 + qd * 2;
        *(float2*)(Og + (size_t)r0 * DMODEL + col) =
            make_float2(o[njo][0] * inv0, o[njo][1] * inv0);
        *(float2*)(Og + (size_t)r1 * DMODEL + col) =
            make_float2(o[njo][2] * inv1, o[njo][3] * inv1);
    }
}

// ---------------------------------------------------------------------------
// Launch
// ---------------------------------------------------------------------------
extern "C" void kernel_launch(void* const* d_in, const int* in_sizes, int n_in,
                              void* d_out, int out_size)
{
    (void)out_size;
    const int X_ELEMS = MTOT * DMODEL;

    const float *x, *Wq, *Wk, *Wv, *Wd;
    if (n_in >= 6 && in_sizes[0] == X_ELEMS) {
        x  = (const float*)d_in[0];
        Wq = (const float*)d_in[2];
        Wk = (const float*)d_in[3];
        Wv = (const float*)d_in[4];
        Wd = (const float*)d_in[5];
    } else {
        Wd = (const float*)d_in[0];
        Wk = (const float*)d_in[1];
        Wq = (const float*)d_in[2];
        Wv = (const float*)d_in[3];
        x  = (const float*)d_in[5];
    }
    float* out = (float*)d_out;

    float *Qp, *Kp, *Vp, *Op;
    cudaGetSymbolAddress((void**)&Qp, g_Q);
    cudaGetSymbolAddress((void**)&Kp, g_K);
    cudaGetSymbolAddress((void**)&Vp, g_V);
    cudaGetSymbolAddress((void**)&Op, g_O);

    dim3 ggrid(DMODEL/128, MTOT/128);   // (16, 32)

    cudaFuncSetAttribute(gemm_bf16x3_kernel,
                         cudaFuncAttributeMaxDynamicSharedMemorySize, GSMEM);
    cudaFuncSetAttribute(attn_mma_kernel,
                         cudaFuncAttributeMaxDynamicSharedMemorySize, ATT_SMEM);

    gemm_bf16x3_kernel<<<ggrid, 512, GSMEM>>>(x, Wq, Qp, 2);   // Q proj + RoPE
    gemm_bf16x3_kernel<<<ggrid, 512, GSMEM>>>(x, Wk, Kp, 2);   // K proj + RoPE
    gemm_bf16x3_kernel<<<ggrid, 512, GSMEM>>>(x, Wv, Vp, 1);   // V proj

    attn_mma_kernel<<<dim3(SS/128, NH, BB), 256, ATT_SMEM>>>(Qp, Kp, Vp, Op);

    gemm_bf16x3_kernel<<<ggrid, 512, GSMEM>>>(Op, Wd, out, 0);
}

// round 10
// speedup vs baseline: 3.0207x; 1.1006x over previous
#include <cuda_runtime.h>
#include <cuda_bf16.h>
#include <math.h>
#include <stdint.h>

// Problem constants
#define BB   2
#define SS   2048
#define DMODEL 2048
#define NH   16
#define DH   128
#define MTOT (BB*SS)

// ---------------------------------------------------------------------------
// Scratch (__device__ globals; allocation-free rule)
// ---------------------------------------------------------------------------
__device__ __nv_bfloat16 g_xh[(size_t)MTOT*DMODEL], g_xl[(size_t)MTOT*DMODEL];
__device__ __nv_bfloat16 g_wqh[(size_t)DMODEL*DMODEL], g_wql[(size_t)DMODEL*DMODEL];
__device__ __nv_bfloat16 g_wkh[(size_t)DMODEL*DMODEL], g_wkl[(size_t)DMODEL*DMODEL];
__device__ __nv_bfloat16 g_wvh[(size_t)DMODEL*DMODEL], g_wvl[(size_t)DMODEL*DMODEL];
__device__ __nv_bfloat16 g_wdh[(size_t)DMODEL*DMODEL], g_wdl[(size_t)DMODEL*DMODEL];
__device__ __nv_bfloat16 g_Qh[(size_t)BB*NH*SS*DH], g_Ql[(size_t)BB*NH*SS*DH];
__device__ __nv_bfloat16 g_Kh[(size_t)BB*NH*SS*DH], g_Kl[(size_t)BB*NH*SS*DH];
__device__ __nv_bfloat16 g_Vh[(size_t)BB*NH*SS*DH], g_Vl[(size_t)BB*NH*SS*DH];
__device__ __nv_bfloat16 g_Oh[(size_t)BB*SS*DMODEL], g_Ol[(size_t)BB*SS*DMODEL];

// ---------------------------------------------------------------------------
// PTX helpers (legacy mma.sync only — tcgen05 is rejected by this toolchain)
// ---------------------------------------------------------------------------
__device__ __forceinline__ unsigned smem_u32(const void* p) {
    return (unsigned)__cvta_generic_to_shared(p);
}
__device__ __forceinline__ void ldsm4(unsigned* r, unsigned addr) {
    asm volatile("ldmatrix.sync.aligned.m8n8.x4.shared.b16 {%0,%1,%2,%3}, [%4];\n"
        : "=r"(r[0]), "=r"(r[1]), "=r"(r[2]), "=r"(r[3]) : "r"(addr));
}
__device__ __forceinline__ void mma16816(float* c, const unsigned* a,
                                         unsigned b0, unsigned b1) {
    asm volatile(
        "mma.sync.aligned.m16n8k16.row.col.f32.bf16.bf16.f32 "
        "{%0,%1,%2,%3}, {%4,%5,%6,%7}, {%8,%9}, {%0,%1,%2,%3};\n"
        : "+f"(c[0]), "+f"(c[1]), "+f"(c[2]), "+f"(c[3])
        : "r"(a[0]), "r"(a[1]), "r"(a[2]), "r"(a[3]), "r"(b0), "r"(b1));
}
__device__ __forceinline__ unsigned packbf2(float x, float y) {
    __nv_bfloat162 t = __floats2bfloat162_rn(x, y);
    return *(unsigned*)&t;
}
__device__ __forceinline__ void cpa16(unsigned dst, const void* src) {
    asm volatile("cp.async.cg.shared.global [%0], [%1], 16;\n" :: "r"(dst), "l"(src));
}
#define CPA_COMMIT() asm volatile("cp.async.commit_group;\n" ::: "memory")
#define CPA_WAIT1()  asm volatile("cp.async.wait_group 1;\n" ::: "memory")

// RoPE factor (reference's rotate_half == identity):
// fac(s,d) = cos(s*inv_freq[d&63]) + sin(s*inv_freq[d&63])
__device__ __forceinline__ float rope_fac(int s, int d) {
    int j = d & 63;
    float inv = expf(-(float)(2*j) * (9.210340371976184f / 128.0f));
    float f = (float)s * inv;
    float sn, cs;
    sincosf(f, &sn, &cs);
    return cs + sn;
}

// ---------------------------------------------------------------------------
// Split fp32 -> bf16 hi/lo
// ---------------------------------------------------------------------------
__global__ void split_kernel(const float4* __restrict__ src,
                             uint2* __restrict__ hi, uint2* __restrict__ lo, int n4)
{
    int i = blockIdx.x * blockDim.x + threadIdx.x;
    if (i >= n4) return;
    float4 v = src[i];
    __nv_bfloat162 h0 = __floats2bfloat162_rn(v.x, v.y);
    __nv_bfloat162 h1 = __floats2bfloat162_rn(v.z, v.w);
    hi[i] = make_uint2(*(unsigned*)&h0, *(unsigned*)&h1);
    __nv_bfloat162 l0 = __floats2bfloat162_rn(v.x - __bfloat162float(h0.x),
                                              v.y - __bfloat162float(h0.y));
    __nv_bfloat162 l1 = __floats2bfloat162_rn(v.z - __bfloat162float(h1.x),
                                              v.w - __bfloat162float(h1.y));
    lo[i] = make_uint2(*(unsigned*)&l0, *(unsigned*)&l1);
}

// ---------------------------------------------------------------------------
// GEMM (legacy HMMA, bf16 split-3, cp.async 3-stage pipeline)
//   C[m][n] = sum_k A[m][k]*B[n][k];  A=Ah+Al, B=Bh+Bl pre-split bf16.
// 256 threads, block tile 128x128x32, warp tile 64x32 (warps 2Mx4N),
// 3 stages x 32KB smem, 2 CTAs/SM.
// grid.z selects weight/output set (QKV fusion). Cout!=null -> fp32 row-major.
// ---------------------------------------------------------------------------
#define STG_BYTES 32768
#define NSTG 3
#define TG_SMEM (NSTG*STG_BYTES)     // 98304
// stage array offsets
#define SA_AH 0
#define SA_AL 8192
#define SA_BH 16384
#define SA_BL 24576

__device__ __forceinline__ unsigned swz_off(int r, int u) {
    return (unsigned)(r * 64 + ((u ^ ((r >> 1) & 3)) << 4));
}

__global__ __launch_bounds__(256, 2)
void gemm_tc2(const __nv_bfloat16* __restrict__ Ain_h, const __nv_bfloat16* __restrict__ Ain_l,
              const __nv_bfloat16* __restrict__ w0h, const __nv_bfloat16* __restrict__ w0l,
              const __nv_bfloat16* __restrict__ w1h, const __nv_bfloat16* __restrict__ w1l,
              const __nv_bfloat16* __restrict__ w2h, const __nv_bfloat16* __restrict__ w2l,
              __nv_bfloat16* __restrict__ d0h, __nv_bfloat16* __restrict__ d0l,
              __nv_bfloat16* __restrict__ d1h, __nv_bfloat16* __restrict__ d1l,
              __nv_bfloat16* __restrict__ d2h, __nv_bfloat16* __restrict__ d2l,
              float* __restrict__ Cout)
{
    extern __shared__ __align__(16) char smem[];
    const unsigned sb = smem_u32(smem);

    const int tid  = threadIdx.x;
    const int lane = tid & 31;
    const int wid  = tid >> 5;
    const int wm   = wid >> 2;        // 0..1  (64 M-rows each)
    const int wn   = wid & 3;         // 0..3  (32 N-cols each)
    const int g    = lane >> 2;       // 0..7
    const int tg   = lane & 3;        // 0..3
    const int bn   = blockIdx.x, bm = blockIdx.y, z = blockIdx.z;

    const __nv_bfloat16* Bh = (z == 0) ? w0h : (z == 1) ? w1h : w2h;
    const __nv_bfloat16* Bl = (z == 0) ? w0l : (z == 1) ? w1l : w2l;
    __nv_bfloat16* Dh = (z == 0) ? d0h : (z == 1) ? d1h : d2h;
    __nv_bfloat16* Dl = (z == 0) ? d0l : (z == 1) ? d1l : d2l;
    const int mode = Cout ? 0 : ((z <= 1) ? 2 : 1);

    const __nv_bfloat16* Ahg = Ain_h + (size_t)(bm * 128) * DMODEL;
    const __nv_bfloat16* Alg = Ain_l + (size_t)(bm * 128) * DMODEL;
    const __nv_bfloat16* Bhg = Bh + (size_t)(bn * 128) * DMODEL;
    const __nv_bfloat16* Blg = Bl + (size_t)(bn * 128) * DMODEL;
    const __nv_bfloat16* srcs[4] = {Ahg, Alg, Bhg, Blg};

    // per-thread staging coords: rep -> arr = rep>>1, r = (rep&1)*64 + tid>>2, u = tid&3
    const int r_lo = tid >> 2;
    const int u_st = tid & 3;

    float acc[4][4][4];   // [m-tile][n8-group][frag]
#pragma unroll
    for (int mt = 0; mt < 4; mt++)
#pragma unroll
        for (int nt = 0; nt < 4; nt++)
#pragma unroll
            for (int e = 0; e < 4; e++) acc[mt][nt][e] = 0.f;

#define ISSUE_STAGE(S, BUF)                                                    \
    do {                                                                       \
        const int k0_ = (S) * 32;                                              \
        const unsigned stb_ = sb + (BUF) * STG_BYTES;                          \
        _Pragma("unroll")                                                      \
        for (int rep = 0; rep < 8; rep++) {                                    \
            const int arr = rep >> 1;                                          \
            const int r   = ((rep & 1) << 6) + r_lo;                           \
            cpa16(stb_ + arr * 8192 + swz_off(r, u_st),                        \
                  srcs[arr] + (size_t)r * DMODEL + k0_ + u_st * 8);            \
        }                                                                      \
    } while (0)

    // prologue: 2 stages in flight
    ISSUE_STAGE(0, 0); CPA_COMMIT();
    ISSUE_STAGE(1, 1); CPA_COMMIT();

    const int NST = DMODEL / 32;   // 64
    int buf = 0, nbuf = 2;
    for (int s = 0; s < NST; s++) {
        CPA_WAIT1();
        __syncthreads();
        if (s + 2 < NST) ISSUE_STAGE(s + 2, nbuf);
        CPA_COMMIT();

        const unsigned stb = sb + buf * STG_BYTES;
#pragma unroll
        for (int ks = 0; ks < 2; ks++) {
            const int u = 2 * ks + (lane >> 4);
            const int ar_base = wm * 64 + (lane & 15);
            const int br_base = wn * 32 + (lane & 15);
            unsigned afr[4][4], bfr[2][4];
            // A-hi, B-hi
#pragma unroll
            for (int mt = 0; mt < 4; mt++)
                ldsm4(afr[mt], stb + SA_AH + swz_off(ar_base + mt * 16, u));
#pragma unroll
            for (int bt = 0; bt < 2; bt++)
                ldsm4(bfr[bt], stb + SA_BH + swz_off(br_base + bt * 16, u));
            // P1: hh
#pragma unroll
            for (int mt = 0; mt < 4; mt++)
#pragma unroll
                for (int nt = 0; nt < 4; nt++)
                    mma16816(acc[mt][nt], afr[mt],
                             bfr[nt >> 1][nt & 1], bfr[nt >> 1][(nt & 1) + 2]);
            // B-lo over bfr; P2: h*l
#pragma unroll
            for (int bt = 0; bt < 2; bt++)
                ldsm4(bfr[bt], stb + SA_BL + swz_off(br_base + bt * 16, u));
#pragma unroll
            for (int mt = 0; mt < 4; mt++)
#pragma unroll
                for (int nt = 0; nt < 4; nt++)
                    mma16816(acc[mt][nt], afr[mt],
                             bfr[nt >> 1][nt & 1], bfr[nt >> 1][(nt & 1) + 2]);
            // A-lo over afr, reload B-hi; P3: l*h
#pragma unroll
            for (int mt = 0; mt < 4; mt++)
                ldsm4(afr[mt], stb + SA_AL + swz_off(ar_base + mt * 16, u));
#pragma unroll
            for (int bt = 0; bt < 2; bt++)
                ldsm4(bfr[bt], stb + SA_BH + swz_off(br_base + bt * 16, u));
#pragma unroll
            for (int mt = 0; mt < 4; mt++)
#pragma unroll
                for (int nt = 0; nt < 4; nt++)
                    mma16816(acc[mt][nt], afr[mt],
                             bfr[nt >> 1][nt & 1], bfr[nt >> 1][(nt & 1) + 2]);
        }
        buf  = (buf  == 2) ? 0 : buf  + 1;
        nbuf = (nbuf == 2) ? 0 : nbuf + 1;
    }
#undef ISSUE_STAGE

    // ---- epilogue ----
#pragma unroll
    for (int mt = 0; mt < 4; mt++) {
#pragma unroll
        for (int nt = 0; nt < 4; nt++) {
            int m0  = bm * 128 + wm * 64 + mt * 16 + g;
            int col = wn * 32 + nt * 8 + tg * 2;
            float v00 = acc[mt][nt][0], v01 = acc[mt][nt][1];
            float v10 = acc[mt][nt][2], v11 = acc[mt][nt][3];
            if (mode == 0) {
                *(float2*)(Cout + (size_t)m0 * DMODEL + bn * 128 + col) = make_float2(v00, v01);
                *(float2*)(Cout + (size_t)(m0 + 8) * DMODEL + bn * 128 + col) = make_float2(v10, v11);
            } else {
                int b0 = m0 >> 11, s0 = m0 & 2047;
                int m1 = m0 + 8;
                int b1 = m1 >> 11, s1 = m1 & 2047;
                if (mode == 2) {
                    v00 *= rope_fac(s0, col); v01 *= rope_fac(s0, col + 1);
                    v10 *= rope_fac(s1, col); v11 *= rope_fac(s1, col + 1);
                }
                size_t i0 = ((size_t)(b0 * NH + bn) * SS + s0) * DH + col;
                size_t i1 = ((size_t)(b1 * NH + bn) * SS + s1) * DH + col;
                __nv_bfloat162 hh;
                hh = __floats2bfloat162_rn(v00, v01);
                *(unsigned*)(Dh + i0) = *(unsigned*)&hh;
                *(unsigned*)(Dl + i0) = packbf2(v00 - __bfloat162float(hh.x),
                                                v01 - __bfloat162float(hh.y));
                hh = __floats2bfloat162_rn(v10, v11);
                *(unsigned*)(Dh + i1) = *(unsigned*)&hh;
                *(unsigned*)(Dl + i1) = packbf2(v10 - __bfloat162float(hh.x),
                                                v11 - __bfloat162float(hh.y));
            }
        }
    }
}

// ---------------------------------------------------------------------------
// Tensor-core causal flash attention (legacy mma.sync, bf16 split-3),
// consumes pre-split bf16 Q/K/V, emits bf16 hi/lo O. (round-7 core)
// ---------------------------------------------------------------------------
#define AQH 0
#define AQL 32768
#define AKH 65536
#define AKL 81920
#define AVH 98304
#define AVL 114688
#define ATT_SMEM 131072

__global__ __launch_bounds__(256, 1)
void attn_mma_kernel(const __nv_bfloat16* __restrict__ Qh, const __nv_bfloat16* __restrict__ Ql,
                     const __nv_bfloat16* __restrict__ Kh, const __nv_bfloat16* __restrict__ Kl,
                     const __nv_bfloat16* __restrict__ Vh, const __nv_bfloat16* __restrict__ Vl,
                     __nv_bfloat16* __restrict__ Oh, __nv_bfloat16* __restrict__ Ol)
{
    extern __shared__ __align__(16) char smem[];
    const unsigned sbm = smem_u32(smem);

    const int tid  = threadIdx.x;
    const int lane = tid & 31;
    const int w    = tid >> 5;
    const int g    = lane >> 2;
    const int qd   = lane & 3;
    const int qt   = blockIdx.x;
    const int h    = blockIdx.y;
    const int b    = blockIdx.z;

    const size_t base = ((size_t)(b*NH + h)) * SS * DH;
    const __nv_bfloat16* Qhg = Qh + base + (size_t)qt * 128 * DH;
    const __nv_bfloat16* Qlg = Ql + base + (size_t)qt * 128 * DH;
    const __nv_bfloat16* Khg = Kh + base;
    const __nv_bfloat16* Klg = Kl + base;
    const __nv_bfloat16* Vhg = Vh + base;
    const __nv_bfloat16* Vlg = Vl + base;

#pragma unroll
    for (int rep = 0; rep < 8; rep++) {
        int idx = tid + rep * 256;
        int r = idx >> 4, u = idx & 15;
        unsigned off = (unsigned)(r * 256 + ((u ^ (r & 7)) << 4));
        *(uint4*)(smem + AQH + off) = *(const uint4*)(Qhg + (size_t)r * DH + u * 8);
        *(uint4*)(smem + AQL + off) = *(const uint4*)(Qlg + (size_t)r * DH + u * 8);
    }

    float o[16][4];
#pragma unroll
    for (int nj = 0; nj < 16; nj++)
#pragma unroll
        for (int e = 0; e < 4; e++) o[nj][e] = 0.f;
    float mrow[2] = {-INFINITY, -INFINITY};
    float lrow[2] = {0.f, 0.f};

    const float scale = 0.08838834764831845f;
    const int ktmax = 2 * qt + 1;

    for (int kt = 0; kt <= ktmax; kt++) {
        __syncthreads();
#pragma unroll
        for (int rep = 0; rep < 4; rep++) {
            int idx = tid + rep * 256;
            int r = idx >> 4, u = idx & 15;
            unsigned off = (unsigned)(r * 256 + ((u ^ (r & 7)) << 4));
            *(uint4*)(smem + AKH + off) = *(const uint4*)(Khg + (size_t)(kt*64 + r) * DH + u * 8);
            *(uint4*)(smem + AKL + off) = *(const uint4*)(Klg + (size_t)(kt*64 + r) * DH + u * 8);
        }
#pragma unroll
        for (int rep = 0; rep < 4; rep++) {
            int idx = tid + rep * 256;
            int kk = idx & 63, u = idx >> 6;
            uint4 hv = *(const uint4*)(Vhg + (size_t)(kt*64 + kk) * DH + u * 8);
            uint4 lv = *(const uint4*)(Vlg + (size_t)(kt*64 + kk) * DH + u * 8);
            const unsigned short* hs = (const unsigned short*)&hv;
            const unsigned short* ls = (const unsigned short*)&lv;
#pragma unroll
            for (int dd = 0; dd < 8; dd++) {
                int d = u * 8 + dd;
                unsigned off = (unsigned)(d * 128 + (((kk >> 3) ^ (d & 7)) << 4) + ((kk & 7) << 1));
                *(unsigned short*)(smem + AVH + off) = hs[dd];
                *(unsigned short*)(smem + AVL + off) = ls[dd];
            }
        }
        __syncthreads();

        float s[8][4];
#pragma unroll
        for (int nj = 0; nj < 8; nj++)
#pragma unroll
            for (int e = 0; e < 4; e++) s[nj][e] = 0.f;

#pragma unroll
        for (int ks = 0; ks < 8; ks++) {
            unsigned ah[4], al[4];
            {
                int row = w * 16 + (lane & 15);
                int u = 2 * ks + (lane >> 4);
                unsigned off = (unsigned)(row * 256 + ((u ^ (row & 7)) << 4));
                ldsm4(ah, sbm + AQH + off);
                ldsm4(al, sbm + AQL + off);
            }
#pragma unroll
            for (int g4 = 0; g4 < 4; g4++) {
                unsigned bh[4], bl[4];
                int row = g4 * 16 + (lane & 15);
                int u = 2 * ks + (lane >> 4);
                unsigned off = (unsigned)(row * 256 + ((u ^ (row & 7)) << 4));
                ldsm4(bh, sbm + AKH + off);
                ldsm4(bl, sbm + AKL + off);
#pragma unroll
                for (int jj = 0; jj < 2; jj++) {
                    int nj = 2 * g4 + jj;
                    mma16816(s[nj], ah, bh[jj], bh[jj + 2]);
                    mma16816(s[nj], ah, bl[jj], bl[jj + 2]);
                    mma16816(s[nj], al, bh[jj], bh[jj + 2]);
                }
            }
        }

        const int r0 = qt * 128 + w * 16 + g;
        const int r1 = r0 + 8;
        const bool tail = (kt >= 2 * qt);
#pragma unroll
        for (int nj = 0; nj < 8; nj++) {
            int c0 = kt * 64 + nj * 8 + qd * 2;
#pragma unroll
            for (int e = 0; e < 4; e++) {
                s[nj][e] *= scale;
                if (tail) {
                    int col = c0 + (e & 1);
                    int row = (e < 2) ? r0 : r1;
                    if (col > row) s[nj][e] = -INFINITY;
                }
            }
        }

        float alpha[2];
#pragma unroll
        for (int half = 0; half < 2; half++) {
            float mx = -INFINITY;
#pragma unroll
            for (int nj = 0; nj < 8; nj++)
                mx = fmaxf(mx, fmaxf(s[nj][2*half], s[nj][2*half+1]));
            mx = fmaxf(mx, __shfl_xor_sync(0xffffffffu, mx, 1));
            mx = fmaxf(mx, __shfl_xor_sync(0xffffffffu, mx, 2));
            float newm = fmaxf(mrow[half], mx);
            float sum = 0.f;
#pragma unroll
            for (int nj = 0; nj < 8; nj++) {
                float p0 = __expf(s[nj][2*half]   - newm);
                float p1 = __expf(s[nj][2*half+1] - newm);
                s[nj][2*half]   = p0;
                s[nj][2*half+1] = p1;
                sum += p0 + p1;
            }
            sum += __shfl_xor_sync(0xffffffffu, sum, 1);
            sum += __shfl_xor_sync(0xffffffffu, sum, 2);
            alpha[half] = __expf(mrow[half] - newm);
            lrow[half] = lrow[half] * alpha[half] + sum;
            mrow[half] = newm;
        }
#pragma unroll
        for (int nj = 0; nj < 16; nj++) {
            o[nj][0] *= alpha[0]; o[nj][1] *= alpha[0];
            o[nj][2] *= alpha[1]; o[nj][3] *= alpha[1];
        }

#pragma unroll
        for (int tpv = 0; tpv < 4; tpv++) {
            unsigned pah[4], pal[4];
            {
                float p00 = s[2*tpv][0],   p01 = s[2*tpv][1];
                float p02 = s[2*tpv][2],   p03 = s[2*tpv][3];
                float p10 = s[2*tpv+1][0], p11 = s[2*tpv+1][1];
                float p12 = s[2*tpv+1][2], p13 = s[2*tpv+1][3];
                __nv_bfloat162 hh;
                hh = __floats2bfloat162_rn(p00, p01); pah[0] = *(unsigned*)&hh;
                pal[0] = packbf2(p00 - __bfloat162float(hh.x), p01 - __bfloat162float(hh.y));
                hh = __floats2bfloat162_rn(p02, p03); pah[1] = *(unsigned*)&hh;
                pal[1] = packbf2(p02 - __bfloat162float(hh.x), p03 - __bfloat162float(hh.y));
                hh = __floats2bfloat162_rn(p10, p11); pah[2] = *(unsigned*)&hh;
                pal[2] = packbf2(p10 - __bfloat162float(hh.x), p11 - __bfloat162float(hh.y));
                hh = __floats2bfloat162_rn(p12, p13); pah[3] = *(unsigned*)&hh;
                pal[3] = packbf2(p12 - __bfloat162float(hh.x), p13 - __bfloat162float(hh.y));
            }
#pragma unroll
            for (int g4 = 0; g4 < 8; g4++) {
                unsigned vbh[4], vbl[4];
                int row = g4 * 16 + (lane & 15);
                int u = 2 * tpv + (lane >> 4);
                unsigned off = (unsigned)(row * 128 + ((u ^ (row & 7)) << 4));
                ldsm4(vbh, sbm + AVH + off);
                ldsm4(vbl, sbm + AVL + off);
#pragma unroll
                for (int jj = 0; jj < 2; jj++) {
                    int njo = 2 * g4 + jj;
                    mma16816(o[njo], pah, vbh[jj], vbh[jj + 2]);
                    mma16816(o[njo], pah, vbl[jj], vbl[jj + 2]);
                    mma16816(o[njo], pal, vbh[jj], vbh[jj + 2]);
                }
            }
        }
    }

    const float inv0 = 1.f / lrow[0];
    const float inv1 = 1.f / lrow[1];
    const int r0 = qt * 128 + w * 16 + g;
    const int r1 = r0 + 8;
    __nv_bfloat16* Ohg = Oh + (size_t)b * SS * DMODEL + (size_t)h * DH;
    __nv_bfloat16* Olg = Ol + (size_t)b * SS * DMODEL + (size_t)h * DH;
#pragma unroll
    for (int njo = 0; njo < 16; njo++) {
        int col = njo * 8 + qd * 2;
        float v0 = o[njo][0] * inv0, v1 = o[njo][1] * inv0;
        float v2 = o[njo][2] * inv1, v3 = o[njo][3] * inv1;
        __nv_bfloat162 hh;
        hh = __floats2bfloat162_rn(v0, v1);
        *(unsigned*)(Ohg + (size_t)r0 * DMODEL + col) = *(unsigned*)&hh;
        *(unsigned*)(Olg + (size_t)r0 * DMODEL + col) =
            packbf2(v0 - __bfloat162float(hh.x), v1 - __bfloat162float(hh.y));
        hh = __floats2bfloat162_rn(v2, v3);
        *(unsigned*)(Ohg + (size_t)r1 * DMODEL + col) = *(unsigned*)&hh;
        *(unsigned*)(Olg + (size_t)r1 * DMODEL + col) =
            packbf2(v2 - __bfloat162float(hh.x), v3 - __bfloat162float(hh.y));
    }
}

// ---------------------------------------------------------------------------
// Launch
// ---------------------------------------------------------------------------
extern "C" void kernel_launch(void* const* d_in, const int* in_sizes, int n_in,
                              void* d_out, int out_size)
{
    (void)out_size;
    const int X_ELEMS = MTOT * DMODEL;

    const float *x, *Wq, *Wk, *Wv, *Wd;
    if (n_in >= 6 && in_sizes[0] == X_ELEMS) {
        x  = (const float*)d_in[0];
        Wq = (const float*)d_in[2];
        Wk = (const float*)d_in[3];
        Wv = (const float*)d_in[4];
        Wd = (const float*)d_in[5];
    } else {
        Wd = (const float*)d_in[0];
        Wk = (const float*)d_in[1];
        Wq = (const float*)d_in[2];
        Wv = (const float*)d_in[3];
        x  = (const float*)d_in[5];
    }
    float* out = (float*)d_out;

    __nv_bfloat16 *xh,*xl,*wqh,*wql,*wkh,*wkl,*wvh,*wvl,*wdh,*wdl;
    __nv_bfloat16 *Qh,*Ql,*Kh,*Kl,*Vh,*Vl,*Oh,*Ol;
    cudaGetSymbolAddress((void**)&xh,  g_xh);  cudaGetSymbolAddress((void**)&xl,  g_xl);
    cudaGetSymbolAddress((void**)&wqh, g_wqh); cudaGetSymbolAddress((void**)&wql, g_wql);
    cudaGetSymbolAddress((void**)&wkh, g_wkh); cudaGetSymbolAddress((void**)&wkl, g_wkl);
    cudaGetSymbolAddress((void**)&wvh, g_wvh); cudaGetSymbolAddress((void**)&wvl, g_wvl);
    cudaGetSymbolAddress((void**)&wdh, g_wdh); cudaGetSymbolAddress((void**)&wdl, g_wdl);
    cudaGetSymbolAddress((void**)&Qh,  g_Qh);  cudaGetSymbolAddress((void**)&Ql,  g_Ql);
    cudaGetSymbolAddress((void**)&Kh,  g_Kh);  cudaGetSymbolAddress((void**)&Kl,  g_Kl);
    cudaGetSymbolAddress((void**)&Vh,  g_Vh);  cudaGetSymbolAddress((void**)&Vl,  g_Vl);
    cudaGetSymbolAddress((void**)&Oh,  g_Oh);  cudaGetSymbolAddress((void**)&Ol,  g_Ol);

    const int XN4 = X_ELEMS / 4;
    const int WN4 = DMODEL * DMODEL / 4;
    split_kernel<<<(XN4 + 255)/256, 256>>>((const float4*)x, (uint2*)xh, (uint2*)xl, XN4);
    split_kernel<<<(WN4 + 255)/256, 256>>>((const float4*)Wq, (uint2*)wqh, (uint2*)wql, WN4);
    split_kernel<<<(WN4 + 255)/256, 256>>>((const float4*)Wk, (uint2*)wkh, (uint2*)wkl, WN4);
    split_kernel<<<(WN4 + 255)/256, 256>>>((const float4*)Wv, (uint2*)wvh, (uint2*)wvl, WN4);
    split_kernel<<<(WN4 + 255)/256, 256>>>((const float4*)Wd, (uint2*)wdh, (uint2*)wdl, WN4);

    cudaFuncSetAttribute(gemm_tc2,
                         cudaFuncAttributeMaxDynamicSharedMemorySize, TG_SMEM);
    cudaFuncSetAttribute(attn_mma_kernel,
                         cudaFuncAttributeMaxDynamicSharedMemorySize, ATT_SMEM);

    // fused Q/K/V projection (+RoPE on Q,K): one launch, grid.z picks the set
    gemm_tc2<<<dim3(DMODEL/128, MTOT/128, 3), 256, TG_SMEM>>>(
        xh, xl,
        wqh, wql, wkh, wkl, wvh, wvl,
        Qh, Ql, Kh, Kl, Vh, Vl,
        nullptr);

    attn_mma_kernel<<<dim3(SS/128, NH, BB), 256, ATT_SMEM>>>(Qh, Ql, Kh, Kl, Vh, Vl, Oh, Ol);

    // output projection -> fp32 out
    gemm_tc2<<<dim3(DMODEL/128, MTOT/128, 1), 256, TG_SMEM>>>(
        Oh, Ol,
        wdh, wdl, wdh, wdl, wdh, wdl,
        nullptr, nullptr, nullptr, nullptr, nullptr, nullptr,
        out);
}